// round 10
// baseline (speedup 1.0000x reference)
#include <cuda_runtime.h>
#include <cuda_bf16.h>
#include <math.h>

#define DDIM  512
#define PCNT  64
#define CCNT  100
#define NBOX  4096
#define G     4
#define MAXWORK 1152

typedef unsigned long long ull;

#define FFMA2(d,a,b,c) asm("fma.rn.f32x2 %0, %1, %2, %3;" : "=l"(d) : "l"(a), "l"(b), "l"(c))
#define FADD2(d,a,b)   asm("add.rn.f32x2 %0, %1, %2;" : "=l"(d) : "l"(a), "l"(b))

__device__ __forceinline__ float pair_sum(ull v) {
    float lo, hi;
    asm("mov.b64 {%0, %1}, %2;" : "=f"(lo), "=f"(hi) : "l"(v));
    return lo + hi;
}

#define MASK2 0x7FFFFFFF7FFFFFFFULL
#define NEG1P 0xBF800000BF800000ULL

// ---- device scratch ----
__device__ float g_pT[CCNT * DDIM * PCNT];   // float2 view [C][256 d2][64 p]
__device__ float g_psq[CCNT * PCNT];
__device__ int   g_off[CCNT];
__device__ int   g_cnt[CCNT];
__device__ int   g_sorted[NBOX];
__device__ int   g_work[MAXWORK];            // (c << 16) | tile
__device__ int   g_nwork;

// =======================================================================
// prep: blocks 0..399 = (class, 16-proto chunk) transpose+psq;
//       block 400 sorts boxes by class and builds the worklist
// =======================================================================
__global__ __launch_bounds__(256) void prep_kernel(
    const float* __restrict__ protos,
    const int*   __restrict__ cls_ids)
{
    const int tid = threadIdx.x;

    if (blockIdx.x == 4 * CCNT) {
        __shared__ int hist[CCNT];
        __shared__ int off[CCNT];
        __shared__ int cur[CCNT];
        __shared__ short ids[NBOX];

        if (tid < CCNT) hist[tid] = 0;
        __syncthreads();
        for (int i = tid; i < NBOX; i += 256) {
            int cc = cls_ids[i];
            ids[i] = (short)cc;
            atomicAdd(&hist[cc], 1);
        }
        __syncthreads();
        if (tid == 0) {
            int run = 0, k = 0;
            for (int c = 0; c < CCNT; c++) {
                int h = hist[c];
                off[c] = run;
                g_off[c] = run;
                g_cnt[c] = h;
                run += h;
                int nt = (h + G - 1) / G;
                for (int t = 0; t < nt; t++) g_work[k++] = (c << 16) | t;
            }
            g_nwork = k;
        }
        __syncthreads();
        if (tid < CCNT) cur[tid] = off[tid];
        __syncthreads();
        for (int i = tid; i < NBOX; i += 256) {
            int cc = ids[i];
            int pos = atomicAdd(&cur[cc], 1);
            g_sorted[pos] = i;
        }
        return;
    }

    // ---- transpose + psq: class c, protos [p0, p0+16) ----
    const int c  = blockIdx.x >> 2;
    const int p0 = (blockIdx.x & 3) * 16;
    __shared__ float buf[16][DDIM + 2];

    const float* src = protos + ((size_t)(c * PCNT + p0)) * DDIM;
    for (int i = tid; i < 16 * DDIM; i += 256) {
        int r = i >> 9, col = i & (DDIM - 1);
        buf[r][col] = src[(size_t)r * DDIM + col];
    }
    __syncthreads();

    {
        const int lane = tid & 31, w = tid >> 5;
        #pragma unroll
        for (int rr = 0; rr < 2; rr++) {
            int row = w + 8 * rr;
            float s = 0.f;
            #pragma unroll
            for (int j = 0; j < 16; j++) {
                float v = buf[row][lane + 32 * j];
                s += v * v;
            }
            #pragma unroll
            for (int o = 16; o > 0; o >>= 1) s += __shfl_down_sync(0xffffffffu, s, o);
            if (lane == 0) g_psq[c * PCNT + p0 + row] = s;
        }
    }

    float* dstbase = g_pT + ((size_t)c * 256) * (PCNT * 2) + p0 * 2;
    for (int i = tid; i < 16 * DDIM; i += 256) {
        int d2 = i >> 5, r = i & 31;
        dstbase[(size_t)d2 * (PCNT * 2) + r] = buf[r >> 1][2 * d2 + (r & 1)];
    }
}

// =======================================================================
// main: block = (class, tile of 4 boxes); warp = (box-pair bp, d-quarter h)
// lane owns protos {2*lane, 2*lane+1}; f32x2-packed 2x2 register tile
// =======================================================================
__global__ __launch_bounds__(256) void proto_match_kernel(
    const float* __restrict__ feats,
    const int*   __restrict__ plabels,
    float* __restrict__ out,
    int N)
{
    if ((int)blockIdx.x >= g_nwork) return;
    const int wk   = g_work[blockIdx.x];
    const int c    = wk >> 16;
    const int tile = wk & 0xffff;
    const int cnt  = g_cnt[c];
    const int cnt_tile = min(G, cnt - tile * G);
    const int start0 = g_off[c] + tile * G;

    const int tid  = threadIdx.x;
    const int lane = tid & 31;
    const int wid  = tid >> 5;
    const int bp   = wid & 1;       // box pair 0..1
    const int h    = wid >> 1;      // d-quarter 0..3

    __shared__ float4 fpack[2][256];      // [pair][d2]: {b0.lo, b0.hi, b1.lo, b1.hi}
    __shared__ float dotp[4][G][PCNT];    // per d-quarter partials
    __shared__ float l1p[4][G][PCNT];
    __shared__ float fsq_sh[G];

    // ---- stage: warps 0..3 load box w's feature row + ||f||^2 ----
    if (wid < G) {
        const int b = wid, pr = b >> 1, side = b & 1;
        int nb = g_sorted[start0 + min(b, cnt_tile - 1)];
        const float4* src = reinterpret_cast<const float4*>(feats + (size_t)nb * DDIM);
        float sq = 0.f;
        #pragma unroll
        for (int j = 0; j < 4; j++) {
            float4 v = __ldg(&src[lane + 32 * j]);
            sq += v.x*v.x + v.y*v.y + v.z*v.z + v.w*v.w;
            int d2a = 2 * (lane + 32 * j);
            *reinterpret_cast<float2*>(&fpack[pr][d2a].x     + 2 * side) = make_float2(v.x, v.y);
            *reinterpret_cast<float2*>(&fpack[pr][d2a + 1].x + 2 * side) = make_float2(v.z, v.w);
        }
        #pragma unroll
        for (int o = 16; o > 0; o >>= 1) sq += __shfl_down_sync(0xffffffffu, sq, o);
        if (lane == 0) fsq_sh[b] = sq;
    }
    __syncthreads();

    // ---- main loop: 64 d2 iterations over this warp's d-quarter ----
    ull da00 = 0, da01 = 0, da10 = 0, da11 = 0;   // dot[box][proto]
    ull la00 = 0, la01 = 0, la10 = 0, la11 = 0;   // l1 [box][proto]

    const ulonglong2* ptV = reinterpret_cast<const ulonglong2*>(g_pT)
                            + (size_t)c * (256 * 32) + lane;
    const ulonglong2* fpV = reinterpret_cast<const ulonglong2*>(&fpack[bp][0]);

    const int d2base = h * 64;
    #pragma unroll 4
    for (int i = 0; i < 64; i++) {
        const int d2 = d2base + i;
        ulonglong2 q  = __ldg(&ptV[(size_t)d2 * 32]);   // .x = proto 2*lane, .y = 2*lane+1
        ulonglong2 ff = fpV[d2];                         // .x = box b0 pair, .y = box b1 pair
        FFMA2(da00, q.x, ff.x, da00);
        FFMA2(da01, q.y, ff.x, da01);
        FFMA2(da10, q.x, ff.y, da10);
        FFMA2(da11, q.y, ff.y, da11);
        ull t0, t1, t2, t3;
        FFMA2(t0, q.x, NEG1P, ff.x); t0 &= MASK2; FADD2(la00, la00, t0);
        FFMA2(t1, q.y, NEG1P, ff.x); t1 &= MASK2; FADD2(la01, la01, t1);
        FFMA2(t2, q.x, NEG1P, ff.y); t2 &= MASK2; FADD2(la10, la10, t2);
        FFMA2(t3, q.y, NEG1P, ff.y); t3 &= MASK2; FADD2(la11, la11, t3);
    }

    // ---- write d-quarter partials ----
    {
        const int b0 = 2 * bp, b1 = 2 * bp + 1;
        const int p0 = 2 * lane, p1 = 2 * lane + 1;
        dotp[h][b0][p0] = pair_sum(da00);  dotp[h][b0][p1] = pair_sum(da01);
        dotp[h][b1][p0] = pair_sum(da10);  dotp[h][b1][p1] = pair_sum(da11);
        l1p[h][b0][p0]  = pair_sum(la00);  l1p[h][b0][p1]  = pair_sum(la01);
        l1p[h][b1][p0]  = pair_sum(la10);  l1p[h][b1][p1]  = pair_sum(la11);
    }
    __syncthreads();

    // ---- epilogue: warp w -> box w (w < 4) ----
    if (wid < G) {
        const int b = wid;
        const bool valid = (b < cnt_tile);
        const int n = g_sorted[start0 + (valid ? b : 0)];
        const float fsq   = fsq_sh[b];
        const float fnorm = fmaxf(sqrtf(fsq), 1e-8f);

        float dt0 = dotp[0][b][lane]      + dotp[1][b][lane]
                  + dotp[2][b][lane]      + dotp[3][b][lane];
        float dt1 = dotp[0][b][lane + 32] + dotp[1][b][lane + 32]
                  + dotp[2][b][lane + 32] + dotp[3][b][lane + 32];
        float la0 = l1p[0][b][lane]       + l1p[1][b][lane]
                  + l1p[2][b][lane]       + l1p[3][b][lane];
        float la1 = l1p[0][b][lane + 32]  + l1p[1][b][lane + 32]
                  + l1p[2][b][lane + 32]  + l1p[3][b][lane + 32];
        float ps0 = g_psq[c * PCNT + lane], ps1 = g_psq[c * PCNT + lane + 32];
        float pn0 = fmaxf(sqrtf(ps0), 1e-8f), pn1 = fmaxf(sqrtf(ps1), 1e-8f);

        float dd0[3], dd1[3];
        dd0[0] = 1.f - dt0 / (fnorm * pn0);
        dd1[0] = 1.f - dt1 / (fnorm * pn1);
        dd0[1] = la0 * (1.f / DDIM);
        dd1[1] = la1 * (1.f / DDIM);
        dd0[2] = (fsq - 2.f * dt0 + ps0) * (1.f / DDIM);
        dd1[2] = (fsq - 2.f * dt1 + ps1) * (1.f / DDIM);

        float avg0 = 0.f, avg1 = 0.f;
        #pragma unroll
        for (int m = 0; m < 3; m++) {
            float s0 = 1.f / (dd0[m] + 1e-5f);
            float s1 = 1.f / (dd1[m] + 1e-5f);
            float mx = fmaxf(s0, s1);
            #pragma unroll
            for (int o = 16; o > 0; o >>= 1) mx = fmaxf(mx, __shfl_xor_sync(0xffffffffu, mx, o));
            float e0 = expf(s0 - mx), e1 = expf(s1 - mx);
            float sum = e0 + e1;
            #pragma unroll
            for (int o = 16; o > 0; o >>= 1) sum += __shfl_xor_sync(0xffffffffu, sum, o);
            float inv = 1.f / sum;
            avg0 += e0 * inv;
            avg1 += e1 * inv;
        }
        avg0 *= (1.f / 3.f);
        avg1 *= (1.f / 3.f);

        if (valid) {
            out[(size_t)N + (size_t)n * PCNT + lane]      = avg0;
            out[(size_t)N + (size_t)n * PCNT + lane + 32] = avg1;
        }

        float a0 = avg0; int i0 = lane;
        if (avg1 > a0) { a0 = avg1; i0 = lane + 32; }
        #pragma unroll
        for (int o = 16; o > 0; o >>= 1) {
            float ao = __shfl_xor_sync(0xffffffffu, a0, o);
            int   io = __shfl_xor_sync(0xffffffffu, i0, o);
            if (ao > a0 || (ao == a0 && io < i0)) { a0 = ao; i0 = io; }
        }
        if (lane == 0 && valid) out[n] = (float)plabels[c * PCNT + i0];
    }
}

extern "C" void kernel_launch(void* const* d_in, const int* in_sizes, int n_in,
                              void* d_out, int out_size) {
    const float* feats   = (const float*)d_in[0];   // [N, 512]
    const float* protos  = (const float*)d_in[1];   // [100, 64, 512]
    const int*   cls_ids = (const int*)d_in[2];     // [N]
    const int*   plabels = (const int*)d_in[3];     // [100, 64]
    float* out = (float*)d_out;

    int N = in_sizes[0] / DDIM;   // 4096

    prep_kernel<<<4 * CCNT + 1, 256>>>(protos, cls_ids);
    proto_match_kernel<<<MAXWORK, 256>>>(feats, plabels, out, N);
}

// round 12
// speedup vs baseline: 1.1565x; 1.1565x over previous
#include <cuda_runtime.h>
#include <cuda_bf16.h>
#include <math.h>

#define DDIM  512
#define PCNT  64
#define CCNT  100
#define NBOX  4096
#define G     8
#define MAXWORK 640

typedef unsigned long long ull;

#define FFMA2(d,a,b,c) asm("fma.rn.f32x2 %0, %1, %2, %3;" : "=l"(d) : "l"(a), "l"(b), "l"(c))
#define FADD2(d,a,b)   asm("add.rn.f32x2 %0, %1, %2;" : "=l"(d) : "l"(a), "l"(b))

__device__ __forceinline__ float pair_sum(ull v) {
    float lo, hi;
    asm("mov.b64 {%0, %1}, %2;" : "=f"(lo), "=f"(hi) : "l"(v));
    return lo + hi;
}

#define MASK2 0x7FFFFFFF7FFFFFFFULL
#define NEG1P 0xBF800000BF800000ULL

// ---- device scratch ----
__device__ float g_pT[CCNT * DDIM * PCNT];   // float2 view [C][256 d2][64 p]
__device__ float g_psq[CCNT * PCNT];
__device__ int   g_off[CCNT];
__device__ int   g_cnt[CCNT];
__device__ int   g_sorted[NBOX];
__device__ int   g_work[MAXWORK];            // (c << 16) | tile
__device__ int   g_nwork;

// =======================================================================
// prep: blocks 0..399 = (class, 16-proto chunk) transpose+psq;
//       block 400 sorts boxes by class and builds the worklist
// =======================================================================
__global__ __launch_bounds__(256) void prep_kernel(
    const float* __restrict__ protos,
    const int*   __restrict__ cls_ids)
{
    const int tid = threadIdx.x;

    if (blockIdx.x == 4 * CCNT) {
        __shared__ int hist[CCNT];
        __shared__ int off[CCNT];
        __shared__ int cur[CCNT];
        __shared__ short ids[NBOX];

        if (tid < CCNT) hist[tid] = 0;
        __syncthreads();
        for (int i = tid; i < NBOX; i += 256) {
            int cc = cls_ids[i];
            ids[i] = (short)cc;
            atomicAdd(&hist[cc], 1);
        }
        __syncthreads();
        if (tid == 0) {
            int run = 0, k = 0;
            for (int c = 0; c < CCNT; c++) {
                int h = hist[c];
                off[c] = run;
                g_off[c] = run;
                g_cnt[c] = h;
                run += h;
                int nt = (h + G - 1) / G;
                for (int t = 0; t < nt; t++) g_work[k++] = (c << 16) | t;
            }
            g_nwork = k;
        }
        __syncthreads();
        if (tid < CCNT) cur[tid] = off[tid];
        __syncthreads();
        for (int i = tid; i < NBOX; i += 256) {
            int cc = ids[i];
            int pos = atomicAdd(&cur[cc], 1);
            g_sorted[pos] = i;
        }
        return;
    }

    // ---- transpose + psq: class c, protos [p0, p0+16) ----
    const int c  = blockIdx.x >> 2;
    const int p0 = (blockIdx.x & 3) * 16;
    __shared__ float buf[16][DDIM + 2];

    const float* src = protos + ((size_t)(c * PCNT + p0)) * DDIM;
    for (int i = tid; i < 16 * DDIM; i += 256) {
        int r = i >> 9, col = i & (DDIM - 1);
        buf[r][col] = src[(size_t)r * DDIM + col];
    }
    __syncthreads();

    {
        const int lane = tid & 31, w = tid >> 5;
        #pragma unroll
        for (int rr = 0; rr < 2; rr++) {
            int row = w + 8 * rr;
            float s = 0.f;
            #pragma unroll
            for (int j = 0; j < 16; j++) {
                float v = buf[row][lane + 32 * j];
                s += v * v;
            }
            #pragma unroll
            for (int o = 16; o > 0; o >>= 1) s += __shfl_down_sync(0xffffffffu, s, o);
            if (lane == 0) g_psq[c * PCNT + p0 + row] = s;
        }
    }

    float* dstbase = g_pT + ((size_t)c * 256) * (PCNT * 2) + p0 * 2;
    for (int i = tid; i < 16 * DDIM; i += 256) {
        int d2 = i >> 5, r = i & 31;
        dstbase[(size_t)d2 * (PCNT * 2) + r] = buf[r >> 1][2 * d2 + (r & 1)];
    }
}

// =======================================================================
// main: block = (class, tile of 8 boxes); warp = (quad q, d-quarter h);
// lane owns 2 protos x 4 boxes — 16 f32x2 accumulators
// =======================================================================
__global__ __launch_bounds__(256, 4) void proto_match_kernel(
    const float* __restrict__ feats,
    const int*   __restrict__ plabels,
    float* __restrict__ out,
    int N)
{
    if ((int)blockIdx.x >= g_nwork) return;
    const int wk   = g_work[blockIdx.x];
    const int c    = wk >> 16;
    const int tile = wk & 0xffff;
    const int cnt  = g_cnt[c];
    const int cnt_tile = min(G, cnt - tile * G);
    const int start0 = g_off[c] + tile * G;

    const int tid  = threadIdx.x;
    const int lane = tid & 31;
    const int wid  = tid >> 5;
    const int q    = wid & 1;       // box quad 0..1
    const int h    = wid >> 1;      // d-quarter 0..3

    __shared__ __align__(16) ull fpack[2][256][6];  // [quad][d2][box-slot 0..3, pad 2] = 24 KB
    __shared__ float dotp[4][G][PCNT];              // 8 KB
    __shared__ float l1p[4][G][PCNT];               // 8 KB
    __shared__ float fsq_sh[G];

    // ---- stage: warp w loads box w's feature row + ||f||^2 ----
    {
        const int b = wid, qq = b >> 2, slot = b & 3;
        int nb = g_sorted[start0 + min(b, cnt_tile - 1)];
        const float4* src = reinterpret_cast<const float4*>(feats + (size_t)nb * DDIM);
        float sq = 0.f;
        #pragma unroll
        for (int j = 0; j < 4; j++) {
            float4 v = __ldg(&src[lane + 32 * j]);
            sq += v.x*v.x + v.y*v.y + v.z*v.z + v.w*v.w;
            int d2a = 2 * (lane + 32 * j);
            float2 lo = make_float2(v.x, v.y);
            float2 hi = make_float2(v.z, v.w);
            fpack[qq][d2a][slot]     = *reinterpret_cast<ull*>(&lo);
            fpack[qq][d2a + 1][slot] = *reinterpret_cast<ull*>(&hi);
        }
        #pragma unroll
        for (int o = 16; o > 0; o >>= 1) sq += __shfl_down_sync(0xffffffffu, sq, o);
        if (lane == 0) fsq_sh[b] = sq;
    }
    __syncthreads();

    // ---- main loop: 64 d2 iterations over this warp's d-quarter ----
    ull da[2][4], la[2][4];
    #pragma unroll
    for (int a = 0; a < 2; a++)
        #pragma unroll
        for (int b = 0; b < 4; b++) { da[a][b] = 0; la[a][b] = 0; }

    const ulonglong2* ptV = reinterpret_cast<const ulonglong2*>(g_pT)
                            + (size_t)c * (256 * 32) + lane;
    const ull* fq = &fpack[q][0][0];

    const int d2base = h * 64;
    #pragma unroll 2
    for (int i = 0; i < 64; i++) {
        const int d2 = d2base + i;
        ulonglong2 pq  = __ldg(&ptV[(size_t)d2 * 32]);   // .x = proto 2*lane, .y = 2*lane+1
        ulonglong2 f01 = *reinterpret_cast<const ulonglong2*>(fq + (size_t)d2 * 6);
        ulonglong2 f23 = *reinterpret_cast<const ulonglong2*>(fq + (size_t)d2 * 6 + 2);

        FFMA2(da[0][0], pq.x, f01.x, da[0][0]);
        FFMA2(da[1][0], pq.y, f01.x, da[1][0]);
        FFMA2(da[0][1], pq.x, f01.y, da[0][1]);
        FFMA2(da[1][1], pq.y, f01.y, da[1][1]);
        FFMA2(da[0][2], pq.x, f23.x, da[0][2]);
        FFMA2(da[1][2], pq.y, f23.x, da[1][2]);
        FFMA2(da[0][3], pq.x, f23.y, da[0][3]);
        FFMA2(da[1][3], pq.y, f23.y, da[1][3]);

        ull t0, t1;
        FFMA2(t0, pq.x, NEG1P, f01.x); t0 &= MASK2; FADD2(la[0][0], la[0][0], t0);
        FFMA2(t1, pq.y, NEG1P, f01.x); t1 &= MASK2; FADD2(la[1][0], la[1][0], t1);
        FFMA2(t0, pq.x, NEG1P, f01.y); t0 &= MASK2; FADD2(la[0][1], la[0][1], t0);
        FFMA2(t1, pq.y, NEG1P, f01.y); t1 &= MASK2; FADD2(la[1][1], la[1][1], t1);
        FFMA2(t0, pq.x, NEG1P, f23.x); t0 &= MASK2; FADD2(la[0][2], la[0][2], t0);
        FFMA2(t1, pq.y, NEG1P, f23.x); t1 &= MASK2; FADD2(la[1][2], la[1][2], t1);
        FFMA2(t0, pq.x, NEG1P, f23.y); t0 &= MASK2; FADD2(la[0][3], la[0][3], t0);
        FFMA2(t1, pq.y, NEG1P, f23.y); t1 &= MASK2; FADD2(la[1][3], la[1][3], t1);
    }

    // ---- write d-quarter partials ----
    {
        const int p0 = 2 * lane;
        #pragma unroll
        for (int j = 0; j < 4; j++) {
            const int b = q * 4 + j;
            dotp[h][b][p0]     = pair_sum(da[0][j]);
            dotp[h][b][p0 + 1] = pair_sum(da[1][j]);
            l1p[h][b][p0]      = pair_sum(la[0][j]);
            l1p[h][b][p0 + 1]  = pair_sum(la[1][j]);
        }
    }
    __syncthreads();

    // ---- epilogue: warp w -> box w ----
    {
        const int b = wid;
        const bool valid = (b < cnt_tile);
        const int n = g_sorted[start0 + (valid ? b : 0)];
        const float fsq   = fsq_sh[b];
        const float fnorm = fmaxf(sqrtf(fsq), 1e-8f);

        float dt0 = dotp[0][b][lane]      + dotp[1][b][lane]
                  + dotp[2][b][lane]      + dotp[3][b][lane];
        float dt1 = dotp[0][b][lane + 32] + dotp[1][b][lane + 32]
                  + dotp[2][b][lane + 32] + dotp[3][b][lane + 32];
        float la0 = l1p[0][b][lane]       + l1p[1][b][lane]
                  + l1p[2][b][lane]       + l1p[3][b][lane];
        float la1 = l1p[0][b][lane + 32]  + l1p[1][b][lane + 32]
                  + l1p[2][b][lane + 32]  + l1p[3][b][lane + 32];
        float ps0 = g_psq[c * PCNT + lane], ps1 = g_psq[c * PCNT + lane + 32];
        float pn0 = fmaxf(sqrtf(ps0), 1e-8f), pn1 = fmaxf(sqrtf(ps1), 1e-8f);

        float dd0[3], dd1[3];
        dd0[0] = 1.f - dt0 / (fnorm * pn0);
        dd1[0] = 1.f - dt1 / (fnorm * pn1);
        dd0[1] = la0 * (1.f / DDIM);
        dd1[1] = la1 * (1.f / DDIM);
        dd0[2] = (fsq - 2.f * dt0 + ps0) * (1.f / DDIM);
        dd1[2] = (fsq - 2.f * dt1 + ps1) * (1.f / DDIM);

        float avg0 = 0.f, avg1 = 0.f;
        #pragma unroll
        for (int m = 0; m < 3; m++) {
            float s0 = 1.f / (dd0[m] + 1e-5f);
            float s1 = 1.f / (dd1[m] + 1e-5f);
            float mx = fmaxf(s0, s1);
            #pragma unroll
            for (int o = 16; o > 0; o >>= 1) mx = fmaxf(mx, __shfl_xor_sync(0xffffffffu, mx, o));
            float e0 = expf(s0 - mx), e1 = expf(s1 - mx);
            float sum = e0 + e1;
            #pragma unroll
            for (int o = 16; o > 0; o >>= 1) sum += __shfl_xor_sync(0xffffffffu, sum, o);
            float inv = 1.f / sum;
            avg0 += e0 * inv;
            avg1 += e1 * inv;
        }
        avg0 *= (1.f / 3.f);
        avg1 *= (1.f / 3.f);

        if (valid) {
            out[(size_t)N + (size_t)n * PCNT + lane]      = avg0;
            out[(size_t)N + (size_t)n * PCNT + lane + 32] = avg1;
        }

        float a0 = avg0; int i0 = lane;
        if (avg1 > a0) { a0 = avg1; i0 = lane + 32; }
        #pragma unroll
        for (int o = 16; o > 0; o >>= 1) {
            float ao = __shfl_xor_sync(0xffffffffu, a0, o);
            int   io = __shfl_xor_sync(0xffffffffu, i0, o);
            if (ao > a0 || (ao == a0 && io < i0)) { a0 = ao; i0 = io; }
        }
        if (lane == 0 && valid) out[n] = (float)plabels[c * PCNT + i0];
    }
}

extern "C" void kernel_launch(void* const* d_in, const int* in_sizes, int n_in,
                              void* d_out, int out_size) {
    const float* feats   = (const float*)d_in[0];   // [N, 512]
    const float* protos  = (const float*)d_in[1];   // [100, 64, 512]
    const int*   cls_ids = (const int*)d_in[2];     // [N]
    const int*   plabels = (const int*)d_in[3];     // [100, 64]
    float* out = (float*)d_out;

    int N = in_sizes[0] / DDIM;   // 4096

    prep_kernel<<<4 * CCNT + 1, 256>>>(protos, cls_ids);
    proto_match_kernel<<<MAXWORK, 256>>>(feats, plabels, out, N);
}

// round 13
// speedup vs baseline: 1.6149x; 1.3964x over previous
#include <cuda_runtime.h>
#include <cuda_bf16.h>
#include <math.h>

#define DDIM  512
#define PCNT  64
#define CCNT  100
#define NBOX  4096
#define G     8
#define MAXWORK 640

typedef unsigned long long ull;

#define FFMA2(d,a,b,c) asm("fma.rn.f32x2 %0, %1, %2, %3;" : "=l"(d) : "l"(a), "l"(b), "l"(c))
#define FADD2(d,a,b)   asm("add.rn.f32x2 %0, %1, %2;" : "=l"(d) : "l"(a), "l"(b))

__device__ __forceinline__ float pair_sum(ull v) {
    float lo, hi;
    asm("mov.b64 {%0, %1}, %2;" : "=f"(lo), "=f"(hi) : "l"(v));
    return lo + hi;
}

#define MASK2 0x7FFFFFFF7FFFFFFFULL
#define NEG1P 0xBF800000BF800000ULL

// ---- device scratch (g_pT padded: unguarded tail prefetch reads +2KB) ----
__device__ float g_pT[CCNT * DDIM * PCNT + 1024];
__device__ float g_psq[CCNT * PCNT];
__device__ int   g_off[CCNT];
__device__ int   g_cnt[CCNT];
__device__ int   g_sorted[NBOX];
__device__ int   g_work[MAXWORK];            // (c << 16) | tile
__device__ int   g_nwork;

// =======================================================================
// prep: blocks 0..799 = (class, 8-proto chunk) transpose+psq;
//       block 800 sorts boxes by class and builds the worklist
// =======================================================================
__global__ __launch_bounds__(256) void prep_kernel(
    const float* __restrict__ protos,
    const int*   __restrict__ cls_ids)
{
    const int tid = threadIdx.x;

    if (blockIdx.x == 8 * CCNT) {
        __shared__ int hist[CCNT];
        __shared__ int off[CCNT];
        __shared__ int cur[CCNT];
        __shared__ int woff[CCNT];
        __shared__ short ids[NBOX];

        if (tid < CCNT) hist[tid] = 0;
        __syncthreads();
        for (int i = tid; i < NBOX; i += 256) {
            int cc = cls_ids[i];
            ids[i] = (short)cc;
            atomicAdd(&hist[cc], 1);
        }
        __syncthreads();
        if (tid == 0) {
            int run = 0, k = 0;
            for (int c = 0; c < CCNT; c++) {
                int h = hist[c];
                off[c] = run;
                g_off[c] = run;
                g_cnt[c] = h;
                run += h;
                woff[c] = k;
                k += (h + G - 1) / G;
            }
            g_nwork = k;
        }
        __syncthreads();
        if (tid < CCNT) {
            cur[tid] = off[tid];
            int nt = (hist[tid] + G - 1) / G;
            int k0 = woff[tid];
            for (int t = 0; t < nt; t++) g_work[k0 + t] = (tid << 16) | t;
        }
        __syncthreads();
        for (int i = tid; i < NBOX; i += 256) {
            int cc = ids[i];
            int pos = atomicAdd(&cur[cc], 1);
            g_sorted[pos] = i;
        }
        return;
    }

    // ---- transpose + psq: class c, protos [p0, p0+8) ----
    const int c  = blockIdx.x >> 3;
    const int p0 = (blockIdx.x & 7) * 8;
    __shared__ float buf[8][DDIM + 2];

    const float* src = protos + ((size_t)(c * PCNT + p0)) * DDIM;
    for (int i = tid; i < 8 * DDIM; i += 256) {
        int r = i >> 9, col = i & (DDIM - 1);
        buf[r][col] = src[(size_t)r * DDIM + col];
    }
    __syncthreads();

    {
        const int lane = tid & 31, w = tid >> 5;
        float s = 0.f;
        #pragma unroll
        for (int j = 0; j < 16; j++) {
            float v = buf[w][lane + 32 * j];
            s += v * v;
        }
        #pragma unroll
        for (int o = 16; o > 0; o >>= 1) s += __shfl_down_sync(0xffffffffu, s, o);
        if (lane == 0) g_psq[c * PCNT + p0 + w] = s;
    }

    // transposed layout: [c][d2 0..255][p 0..63][2]; this block owns p0..p0+7
    float* dstbase = g_pT + ((size_t)c * 256) * (PCNT * 2) + p0 * 2;
    for (int i = tid; i < 8 * DDIM; i += 256) {
        int d2 = i >> 4, r = i & 15;              // r = local proto*2 + dim-in-pair
        dstbase[(size_t)d2 * (PCNT * 2) + r] = buf[r >> 1][2 * d2 + (r & 1)];
    }
}

// =======================================================================
// main: block = (class, tile of 8 boxes); warp = (quad q, d-quarter h);
// lane owns 2 protos x 4 boxes; 4-deep LDG prefetch pipeline
// =======================================================================
__global__ __launch_bounds__(256, 3) void proto_match_kernel(
    const float* __restrict__ feats,
    const int*   __restrict__ plabels,
    float* __restrict__ out,
    int N)
{
    if ((int)blockIdx.x >= g_nwork) return;
    const int wk   = g_work[blockIdx.x];
    const int c    = wk >> 16;
    const int tile = wk & 0xffff;
    const int cnt  = g_cnt[c];
    const int cnt_tile = min(G, cnt - tile * G);
    const int start0 = g_off[c] + tile * G;

    const int tid  = threadIdx.x;
    const int lane = tid & 31;
    const int wid  = tid >> 5;
    const int q    = wid & 1;       // box quad 0..1
    const int h    = wid >> 1;      // d-quarter 0..3

    __shared__ __align__(16) ull fpack[2][256][6];  // [quad][d2][slot0..3, pad2]
    __shared__ float dotp[4][G][PCNT];
    __shared__ float l1p[4][G][PCNT];
    __shared__ float fsq_sh[G];

    // ---- stage: warp w loads box w's feature row + ||f||^2 ----
    {
        const int b = wid, qq = b >> 2, slot = b & 3;
        int nb = g_sorted[start0 + min(b, cnt_tile - 1)];
        const float4* src = reinterpret_cast<const float4*>(feats + (size_t)nb * DDIM);
        float sq = 0.f;
        #pragma unroll
        for (int j = 0; j < 4; j++) {
            float4 v = __ldg(&src[lane + 32 * j]);
            sq += v.x*v.x + v.y*v.y + v.z*v.z + v.w*v.w;
            int d2a = 2 * (lane + 32 * j);
            float2 lo = make_float2(v.x, v.y);
            float2 hi = make_float2(v.z, v.w);
            fpack[qq][d2a][slot]     = *reinterpret_cast<ull*>(&lo);
            fpack[qq][d2a + 1][slot] = *reinterpret_cast<ull*>(&hi);
        }
        #pragma unroll
        for (int o = 16; o > 0; o >>= 1) sq += __shfl_down_sync(0xffffffffu, sq, o);
        if (lane == 0) fsq_sh[b] = sq;
    }
    __syncthreads();

    // ---- main loop with 4-deep prefetch ----
    ull da[2][4], la[2][4];
    #pragma unroll
    for (int a = 0; a < 2; a++)
        #pragma unroll
        for (int b = 0; b < 4; b++) { da[a][b] = 0; la[a][b] = 0; }

    const ulonglong2* ptV = reinterpret_cast<const ulonglong2*>(g_pT)
                            + ((size_t)c * 256 + h * 64) * 32 + lane;
    const ull* fq = &fpack[q][h * 64][0];

    ulonglong2 qb[4];
    #pragma unroll
    for (int j = 0; j < 4; j++) qb[j] = __ldg(&ptV[(size_t)j * 32]);

    #pragma unroll 2
    for (int i = 0; i < 64; i += 4) {
        #pragma unroll
        for (int j = 0; j < 4; j++) {
            ulonglong2 pq = qb[j];
            qb[j] = __ldg(&ptV[(size_t)(i + 4 + j) * 32]);   // tail reads pad
            ulonglong2 f01 = *reinterpret_cast<const ulonglong2*>(fq + (size_t)(i + j) * 6);
            ulonglong2 f23 = *reinterpret_cast<const ulonglong2*>(fq + (size_t)(i + j) * 6 + 2);

            FFMA2(da[0][0], pq.x, f01.x, da[0][0]);
            FFMA2(da[1][0], pq.y, f01.x, da[1][0]);
            FFMA2(da[0][1], pq.x, f01.y, da[0][1]);
            FFMA2(da[1][1], pq.y, f01.y, da[1][1]);
            FFMA2(da[0][2], pq.x, f23.x, da[0][2]);
            FFMA2(da[1][2], pq.y, f23.x, da[1][2]);
            FFMA2(da[0][3], pq.x, f23.y, da[0][3]);
            FFMA2(da[1][3], pq.y, f23.y, da[1][3]);

            ull t0, t1;
            FFMA2(t0, pq.x, NEG1P, f01.x); t0 &= MASK2; FADD2(la[0][0], la[0][0], t0);
            FFMA2(t1, pq.y, NEG1P, f01.x); t1 &= MASK2; FADD2(la[1][0], la[1][0], t1);
            FFMA2(t0, pq.x, NEG1P, f01.y); t0 &= MASK2; FADD2(la[0][1], la[0][1], t0);
            FFMA2(t1, pq.y, NEG1P, f01.y); t1 &= MASK2; FADD2(la[1][1], la[1][1], t1);
            FFMA2(t0, pq.x, NEG1P, f23.x); t0 &= MASK2; FADD2(la[0][2], la[0][2], t0);
            FFMA2(t1, pq.y, NEG1P, f23.x); t1 &= MASK2; FADD2(la[1][2], la[1][2], t1);
            FFMA2(t0, pq.x, NEG1P, f23.y); t0 &= MASK2; FADD2(la[0][3], la[0][3], t0);
            FFMA2(t1, pq.y, NEG1P, f23.y); t1 &= MASK2; FADD2(la[1][3], la[1][3], t1);
        }
    }

    // ---- write d-quarter partials ----
    {
        const int p0 = 2 * lane;
        #pragma unroll
        for (int j = 0; j < 4; j++) {
            const int b = q * 4 + j;
            dotp[h][b][p0]     = pair_sum(da[0][j]);
            dotp[h][b][p0 + 1] = pair_sum(da[1][j]);
            l1p[h][b][p0]      = pair_sum(la[0][j]);
            l1p[h][b][p0 + 1]  = pair_sum(la[1][j]);
        }
    }
    __syncthreads();

    // ---- epilogue: warp w -> box w ----
    {
        const int b = wid;
        const bool valid = (b < cnt_tile);
        const int n = g_sorted[start0 + (valid ? b : 0)];
        const float fsq   = fsq_sh[b];
        const float fnorm = fmaxf(sqrtf(fsq), 1e-8f);

        float dt0 = dotp[0][b][lane]      + dotp[1][b][lane]
                  + dotp[2][b][lane]      + dotp[3][b][lane];
        float dt1 = dotp[0][b][lane + 32] + dotp[1][b][lane + 32]
                  + dotp[2][b][lane + 32] + dotp[3][b][lane + 32];
        float la0 = l1p[0][b][lane]       + l1p[1][b][lane]
                  + l1p[2][b][lane]       + l1p[3][b][lane];
        float la1 = l1p[0][b][lane + 32]  + l1p[1][b][lane + 32]
                  + l1p[2][b][lane + 32]  + l1p[3][b][lane + 32];
        float ps0 = g_psq[c * PCNT + lane], ps1 = g_psq[c * PCNT + lane + 32];
        float pn0 = fmaxf(sqrtf(ps0), 1e-8f), pn1 = fmaxf(sqrtf(ps1), 1e-8f);

        float dd0[3], dd1[3];
        dd0[0] = 1.f - dt0 / (fnorm * pn0);
        dd1[0] = 1.f - dt1 / (fnorm * pn1);
        dd0[1] = la0 * (1.f / DDIM);
        dd1[1] = la1 * (1.f / DDIM);
        dd0[2] = (fsq - 2.f * dt0 + ps0) * (1.f / DDIM);
        dd1[2] = (fsq - 2.f * dt1 + ps1) * (1.f / DDIM);

        float avg0 = 0.f, avg1 = 0.f;
        #pragma unroll
        for (int m = 0; m < 3; m++) {
            float s0 = 1.f / (dd0[m] + 1e-5f);
            float s1 = 1.f / (dd1[m] + 1e-5f);
            float mx = fmaxf(s0, s1);
            #pragma unroll
            for (int o = 16; o > 0; o >>= 1) mx = fmaxf(mx, __shfl_xor_sync(0xffffffffu, mx, o));
            float e0 = expf(s0 - mx), e1 = expf(s1 - mx);
            float sum = e0 + e1;
            #pragma unroll
            for (int o = 16; o > 0; o >>= 1) sum += __shfl_xor_sync(0xffffffffu, sum, o);
            float inv = 1.f / sum;
            avg0 += e0 * inv;
            avg1 += e1 * inv;
        }
        avg0 *= (1.f / 3.f);
        avg1 *= (1.f / 3.f);

        if (valid) {
            out[(size_t)N + (size_t)n * PCNT + lane]      = avg0;
            out[(size_t)N + (size_t)n * PCNT + lane + 32] = avg1;
        }

        float a0 = avg0; int i0 = lane;
        if (avg1 > a0) { a0 = avg1; i0 = lane + 32; }
        #pragma unroll
        for (int o = 16; o > 0; o >>= 1) {
            float ao = __shfl_xor_sync(0xffffffffu, a0, o);
            int   io = __shfl_xor_sync(0xffffffffu, i0, o);
            if (ao > a0 || (ao == a0 && io < i0)) { a0 = ao; i0 = io; }
        }
        if (lane == 0 && valid) out[n] = (float)plabels[c * PCNT + i0];
    }
}

extern "C" void kernel_launch(void* const* d_in, const int* in_sizes, int n_in,
                              void* d_out, int out_size) {
    const float* feats   = (const float*)d_in[0];   // [N, 512]
    const float* protos  = (const float*)d_in[1];   // [100, 64, 512]
    const int*   cls_ids = (const int*)d_in[2];     // [N]
    const int*   plabels = (const int*)d_in[3];     // [100, 64]
    float* out = (float*)d_out;

    int N = in_sizes[0] / DDIM;   // 4096

    prep_kernel<<<8 * CCNT + 1, 256>>>(protos, cls_ids);
    proto_match_kernel<<<MAXWORK, 256>>>(feats, plabels, out, N);
}